// round 3
// baseline (speedup 1.0000x reference)
#include <cuda_runtime.h>
#include <cfloat>

#define Bn 16
#define Cn 64
#define Nn 2048
#define On 64
#define Kn 20
#define CNT_TOT (16*2048*20)

// ---------------- scratch (static device globals; no runtime allocation) ----------------
__device__ float  g_D[(size_t)Bn*Nn*Nn];     // 256 MB neg_dist scratch
__device__ float  g_xx[Bn*Nn];               // squared norms
__device__ int    g_idx[Bn*Nn*Kn];           // top-K index sets (order arbitrary)
__device__ float  g_U[(size_t)Bn*Nn*On];     // U[b][m][o] = Wd . x  (o contiguous)
__device__ float  g_Bse[(size_t)Bn*Nn*On];   // (V-U)[b][n][o]
__device__ double g_sum[On], g_sumsq[On];
__device__ float  g_scale[On], g_shift[On];

// ---------------- kernel 0: zero the stats accumulators (graph replays!) ----------------
__global__ void k_zero() {
    int o = threadIdx.x;
    g_sum[o] = 0.0; g_sumsq[o] = 0.0;
}

// ---------------- kernel 1: xx[b,n] = sum_c x^2 ----------------
__global__ void k_xx(const float* __restrict__ x) {
    int id = blockIdx.x * blockDim.x + threadIdx.x;   // 0 .. B*N-1
    if (id >= Bn * Nn) return;
    int b = id / Nn, n = id % Nn;
    const float* xp = x + (size_t)b * Cn * Nn + n;
    float s = 0.f;
#pragma unroll
    for (int c = 0; c < Cn; c++) {
        float v = xp[(size_t)c * Nn];
        s = fmaf(v, v, s);
    }
    g_xx[id] = s;
}

// ---------------- kernel 2: neg_dist 128x128 tiles, 8x8 per thread ----------------
// Triangular grid (tm >= tn); mirror written via smem transpose.
__global__ void __launch_bounds__(256) k_gram(const float* __restrict__ x) {
    __shared__ __align__(16) float sh[64 * 132];   // 33.8KB: As|Bs during compute, Ts after

    int t = blockIdx.x, b = blockIdx.y;
    int tm = (int)((sqrtf(8.f * t + 1.f) - 1.f) * 0.5f);
    while ((tm + 1) * (tm + 2) / 2 <= t) tm++;
    while (tm * (tm + 1) / 2 > t) tm--;
    int tn = t - tm * (tm + 1) / 2;

    int n0 = tn * 128, m0 = tm * 128;
    const float* xb = x + (size_t)b * Cn * Nn;
    int tid = threadIdx.x, tx = tid & 15, ty = tid >> 4;

    float* As = sh;            // [32][128]
    float* Bs = sh + 32 * 128; // [32][128]

    float acc[8][8] = {};

    for (int kc = 0; kc < 64; kc += 32) {
        __syncthreads();
#pragma unroll
        for (int i = 0; i < 4; i++) {
            int f = tid + 256 * i;          // float4 index over 1024
            int c = f >> 5, c4 = (f & 31) * 4;
            *(float4*)&As[c * 128 + c4] = *(const float4*)&xb[(size_t)(kc + c) * Nn + n0 + c4];
            *(float4*)&Bs[c * 128 + c4] = *(const float4*)&xb[(size_t)(kc + c) * Nn + m0 + c4];
        }
        __syncthreads();
#pragma unroll 4
        for (int c = 0; c < 32; c++) {
            float4 a0 = *(float4*)&As[c * 128 + ty * 4];
            float4 a1 = *(float4*)&As[c * 128 + 64 + ty * 4];
            float4 b0 = *(float4*)&Bs[c * 128 + tx * 4];
            float4 b1 = *(float4*)&Bs[c * 128 + 64 + tx * 4];
            float av[8] = {a0.x, a0.y, a0.z, a0.w, a1.x, a1.y, a1.z, a1.w};
            float bv[8] = {b0.x, b0.y, b0.z, b0.w, b1.x, b1.y, b1.z, b1.w};
#pragma unroll
            for (int i = 0; i < 8; i++)
#pragma unroll
                for (int j = 0; j < 8; j++)
                    acc[i][j] = fmaf(av[i], bv[j], acc[i][j]);
        }
    }

    float xn[8], xm[8];
#pragma unroll
    for (int i = 0; i < 4; i++) {
        xn[i]     = g_xx[b * Nn + n0 + ty * 4 + i];
        xn[4 + i] = g_xx[b * Nn + n0 + 64 + ty * 4 + i];
        xm[i]     = g_xx[b * Nn + m0 + tx * 4 + i];
        xm[4 + i] = g_xx[b * Nn + m0 + 64 + tx * 4 + i];
    }

    float vv[8][8];
#pragma unroll
    for (int i = 0; i < 8; i++)
#pragma unroll
        for (int j = 0; j < 8; j++)
            vv[i][j] = 2.f * acc[i][j] - xn[i] - xm[j];

    float* Db = g_D + (size_t)b * Nn * Nn;

    // direct store: D[n][m]
#pragma unroll
    for (int i = 0; i < 8; i++) {
        int nl = (i < 4) ? (ty * 4 + i) : (64 + ty * 4 + i - 4);
        *(float4*)&Db[(size_t)(n0 + nl) * Nn + m0 + tx * 4] =
            make_float4(vv[i][0], vv[i][1], vv[i][2], vv[i][3]);
        *(float4*)&Db[(size_t)(n0 + nl) * Nn + m0 + 64 + tx * 4] =
            make_float4(vv[i][4], vv[i][5], vv[i][6], vv[i][7]);
    }

    // mirror store: D[m][n] via smem transpose (two 64-col halves)
    if (tm != tn) {
        float* Ts = sh;                       // [64][132]
#pragma unroll
        for (int h = 0; h < 2; h++) {
            __syncthreads();
#pragma unroll
            for (int i = 0; i < 8; i++) {
                int nl = (i < 4) ? (ty * 4 + i) : (64 + ty * 4 + i - 4);
#pragma unroll
                for (int j = 0; j < 4; j++)
                    Ts[(tx * 4 + j) * 132 + nl] = vv[i][h * 4 + j];
            }
            __syncthreads();
#pragma unroll
            for (int q = 0; q < 8; q++) {
                int f = tid + 256 * q;        // over 64*32 float4
                int mc = f >> 5, n4 = (f & 31) * 4;
                float4 w = *(float4*)&Ts[mc * 132 + n4];
                *(float4*)&Db[(size_t)(m0 + h * 64 + mc) * Nn + n0 + n4] = w;
            }
        }
    }
}

// ---------------- kernel 3: top-K=20 per row via single-pass 11-bit histogram select ----
// Only the SET of top-K indices matters downstream; threshold-bin ties resolved
// by exact (key desc, index asc) rank -> identical set to stable top_k.
__global__ void __launch_bounds__(256) k_topk() {
    int row = blockIdx.x;                       // b*N + n
    const float4* d4 = (const float4*)(g_D + (size_t)row * Nn);
    int tid = threadIdx.x;                      // 256 threads, 8 elems each

    __shared__ int      hist[2049];             // becomes sgt[] (suffix counts) in place
    __shared__ int      wtot[8];
    __shared__ int      s_win, s_kp, s_base, s_cnt, s_ccnt;
    __shared__ unsigned cand_key[2048];
    __shared__ int      cand_idx[2048];

    // load + convert to order-preserving uint keys (bigger key = bigger float)
    unsigned key[8];
    int      bin[8];
    {
        float4 a = d4[tid * 2], b = d4[tid * 2 + 1];
        float f[8] = {a.x, a.y, a.z, a.w, b.x, b.y, b.z, b.w};
#pragma unroll
        for (int i = 0; i < 8; i++) {
            unsigned u = __float_as_uint(f[i]);
            key[i] = ((int)u < 0) ? ~u : (u | 0x80000000u);
            bin[i] = key[i] >> 21;              // top 11 bits
        }
    }

#pragma unroll
    for (int j = 0; j < 8; j++) hist[tid * 8 + j] = 0;
    if (tid == 0) { hist[2048] = 0; s_cnt = 0; s_ccnt = 0; }
    __syncthreads();

#pragma unroll
    for (int i = 0; i < 8; i++) atomicAdd(&hist[bin[i]], 1);
    __syncthreads();

    // suffix counts: sgt[b] = #elems with bin >= b (computed in place over hist)
    int h[8], loc[8];
#pragma unroll
    for (int j = 0; j < 8; j++) h[j] = hist[tid * 8 + j];
    int run = 0;
#pragma unroll
    for (int j = 7; j >= 0; j--) { run += h[j]; loc[j] = run; }

    int lane = tid & 31, warp = tid >> 5;
    int inc = run;
#pragma unroll
    for (int off = 1; off < 32; off <<= 1) {
        int v = __shfl_down_sync(0xffffffffu, inc, off);
        if (lane + off < 32) inc += v;
    }
    if (lane == 0) wtot[warp] = inc;            // warp total
    __syncthreads();
    int offs = 0;
#pragma unroll
    for (int w = 0; w < 8; w++) if (w > warp) offs += wtot[w];
    int above = (inc - run) + offs;             // elems in bins > my last bin
#pragma unroll
    for (int j = 0; j < 8; j++) hist[tid * 8 + j] = loc[j] + above;
    if (tid == 0) hist[2048] = 0;
    __syncthreads();

    // find threshold bin: sgt[b] >= K > sgt[b+1]
#pragma unroll
    for (int j = 0; j < 8; j++) {
        int bb = tid * 8 + j;
        int cg = hist[bb], cgn = hist[bb + 1];
        if (cg >= Kn && cgn < Kn) { s_win = bb; s_kp = Kn - cgn; s_base = cgn; }
    }
    __syncthreads();
    int win = s_win;

    int* op = g_idx + row * Kn;
#pragma unroll
    for (int i = 0; i < 8; i++) {
        int e = tid * 8 + i;
        if (bin[i] > win) {
            op[atomicAdd(&s_cnt, 1)] = e;       // definitely in top-K (order arbitrary)
        } else if (bin[i] == win) {
            int p = atomicAdd(&s_ccnt, 1);
            cand_key[p] = key[i]; cand_idx[p] = e;
        }
    }
    __syncthreads();

    int cc = s_ccnt, kp = s_kp, base = s_base;
    for (int i = tid; i < cc; i += 256) {       // exact rank among candidates
        unsigned ki = cand_key[i];
        int      xi = cand_idx[i];
        int r = 0;
        for (int j = 0; j < cc; j++) {
            unsigned kj = cand_key[j];
            r += (kj > ki) || (kj == ki && cand_idx[j] < xi);
        }
        if (r < kp) op[base + r] = xi;
    }
}

// ---------------- kernel 4: U = Wd.x , Bse = (Wc-Wd).x  (o-contiguous layout) -----------
__global__ void k_uv(const float* __restrict__ x, const float* __restrict__ W) {
    int b = blockIdx.y;
    int m0 = blockIdx.x * 64;
    __shared__ float Wd[64 * 64];   // [c][o]
    __shared__ float Wf[64 * 64];   // [c][o]  (Wc - Wd)
    __shared__ float xs[64 * 64];   // [c][m]
    int tid = threadIdx.x;
#pragma unroll
    for (int i = 0; i < 16; i++) {
        int id = tid + 256 * i;
        int o = id >> 6, c = id & 63;
        float wd = W[o * 128 + c];
        float wc = W[o * 128 + 64 + c];
        Wd[c * 64 + o] = wd;
        Wf[c * 64 + o] = wc - wd;
        xs[id] = x[(size_t)b * Cn * Nn + (size_t)(id >> 6) * Nn + m0 + (id & 63)];
    }
    __syncthreads();

    int o = tid & 63, mq = tid >> 6;
    float aU[16], aD[16];
#pragma unroll
    for (int t = 0; t < 16; t++) { aU[t] = 0.f; aD[t] = 0.f; }

    for (int c = 0; c < 64; c++) {
        float wu = Wd[c * 64 + o];
        float wf = Wf[c * 64 + o];
#pragma unroll
        for (int t = 0; t < 16; t++) {
            float xv = xs[c * 64 + mq + t * 4];   // broadcast within warp
            aU[t] = fmaf(wu, xv, aU[t]);
            aD[t] = fmaf(wf, xv, aD[t]);
        }
    }
#pragma unroll
    for (int t = 0; t < 16; t++) {
        int m = m0 + mq + t * 4;
        g_U  [((size_t)b * Nn + m) * On + o] = aU[t];
        g_Bse[((size_t)b * Nn + m) * On + o] = aD[t];
    }
}

// ---------------- kernel 5: per-channel sum / sumsq of y over (b,n,k) ----------------
__global__ void k_stats() {
    int b = blockIdx.y;
    int n0 = blockIdx.x * 128;
    int tid = threadIdx.x;
    int o = tid & 63, g = tid >> 6;
    float s = 0.f, s2 = 0.f;
    for (int j = 0; j < 32; j++) {
        int n = n0 + g * 32 + j;
        float bse = g_Bse[((size_t)b * Nn + n) * On + o];
        const int* ip = g_idx + (b * Nn + n) * Kn;
#pragma unroll
        for (int k = 0; k < Kn; k++) {
            int m = ip[k];
            float y = g_U[((size_t)b * Nn + m) * On + o] + bse;
            s += y;
            s2 = fmaf(y, y, s2);
        }
    }
    __shared__ float ss[4][64], ss2[4][64];
    ss[g][o] = s; ss2[g][o] = s2;
    __syncthreads();
    if (g == 0) {
        double ts = (double)ss[0][o] + (double)ss[1][o] + (double)ss[2][o] + (double)ss[3][o];
        double t2 = (double)ss2[0][o] + (double)ss2[1][o] + (double)ss2[2][o] + (double)ss2[3][o];
        atomicAdd(&g_sum[o], ts);
        atomicAdd(&g_sumsq[o], t2);
    }
}

// ---------------- kernel 6: finalize BN affine ----------------
__global__ void k_fin(const float* __restrict__ gamma, const float* __restrict__ beta) {
    int o = threadIdx.x;
    double mean = g_sum[o] / (double)CNT_TOT;
    double var  = g_sumsq[o] / (double)CNT_TOT - mean * mean;
    float sc = gamma[o] * rsqrtf((float)var + 1e-5f);
    g_scale[o] = sc;
    g_shift[o] = beta[o] - (float)mean * sc;
}

// ---------------- kernel 7: normalize + leaky relu + max over k -> out[b][o][n] --------
__global__ void k_out(float* __restrict__ out) {
    int b = blockIdx.y;
    int n0 = blockIdx.x * 32;
    int tid = threadIdx.x;
    int o = tid & 63, nq = tid >> 6;
    __shared__ float sm[64 * 33];
    float sc = g_scale[o], sh = g_shift[o];
    for (int j = 0; j < 8; j++) {
        int nl = nq * 8 + j;
        int n = n0 + nl;
        float bse = g_Bse[((size_t)b * Nn + n) * On + o];
        const int* ip = g_idx + (b * Nn + n) * Kn;
        float mx = -FLT_MAX;
#pragma unroll
        for (int k = 0; k < Kn; k++) {
            int m = ip[k];
            float y  = g_U[((size_t)b * Nn + m) * On + o] + bse;
            float yn = fmaf(y, sc, sh);
            float a  = (yn >= 0.f) ? yn : 0.2f * yn;
            mx = fmaxf(mx, a);
        }
        sm[o * 33 + nl] = mx;
    }
    __syncthreads();
    int nl2 = tid & 31, og = tid >> 5;
#pragma unroll
    for (int j = 0; j < 8; j++) {
        int o2 = og * 8 + j;
        out[((size_t)b * On + o2) * Nn + n0 + nl2] = sm[o2 * 33 + nl2];
    }
}

// ---------------- launch ----------------
extern "C" void kernel_launch(void* const* d_in, const int* in_sizes, int n_in,
                              void* d_out, int out_size) {
    const float* x     = (const float*)d_in[0];
    const float* W     = (const float*)d_in[1];
    const float* gamma = (const float*)d_in[2];
    const float* beta  = (const float*)d_in[3];
    float* out = (float*)d_out;

    k_zero<<<1, 64>>>();
    k_xx<<<(Bn * Nn) / 256, 256>>>(x);

    dim3 gg(136, 16);                 // triangular tile set, 128x128 tiles
    k_gram<<<gg, 256>>>(x);

    k_topk<<<Bn * Nn, 256>>>();

    dim3 guv(Nn / 64, Bn);
    k_uv<<<guv, 256>>>(x, W);

    dim3 gst(16, Bn);
    k_stats<<<gst, 256>>>();

    k_fin<<<1, 64>>>(gamma, beta);

    dim3 go(Nn / 32, Bn);
    k_out<<<go, 256>>>(out);
}

// round 4
// speedup vs baseline: 1.1788x; 1.1788x over previous
#include <cuda_runtime.h>
#include <cfloat>

#define Bn 16
#define Cn 64
#define Nn 2048
#define On 64
#define Kn 20
#define CNT_TOT (16*2048*20)

// ---------------- scratch (static device globals; no runtime allocation) ----------------
__device__ float  g_D[(size_t)Bn*Nn*Nn];     // 256 MB neg_dist scratch
__device__ float  g_xx[Bn*Nn];               // squared norms
__device__ int    g_idx[Bn*Nn*Kn];           // top-K index sets (order arbitrary)
__device__ float  g_U[(size_t)Bn*Nn*On];     // U[b][m][o] = Wd . x  (o contiguous)
__device__ float  g_Bse[(size_t)Bn*Nn*On];   // (V-U)[b][n][o]
__device__ double g_sum[On], g_sumsq[On];
__device__ float  g_scale[On], g_shift[On];

// ---------------- kernel 0: zero the stats accumulators (graph replays!) ----------------
__global__ void k_zero() {
    int o = threadIdx.x;
    g_sum[o] = 0.0; g_sumsq[o] = 0.0;
}

// ---------------- kernel 1: xx[b,n] = sum_c x^2 ----------------
__global__ void k_xx(const float* __restrict__ x) {
    int id = blockIdx.x * blockDim.x + threadIdx.x;   // 0 .. B*N-1
    if (id >= Bn * Nn) return;
    int b = id / Nn, n = id % Nn;
    const float* xp = x + (size_t)b * Cn * Nn + n;
    float s = 0.f;
#pragma unroll
    for (int c = 0; c < Cn; c++) {
        float v = xp[(size_t)c * Nn];
        s = fmaf(v, v, s);
    }
    g_xx[id] = s;
}

// ---------------- kernel 2: neg_dist 128x128 tiles, 8x8 per thread ----------------
// Triangular grid (tm >= tn); mirror written via smem transpose.
__global__ void __launch_bounds__(256) k_gram(const float* __restrict__ x) {
    __shared__ __align__(16) float sh[64 * 132];   // As|Bs during compute, Ts after

    int t = blockIdx.x, b = blockIdx.y;
    int tm = (int)((sqrtf(8.f * t + 1.f) - 1.f) * 0.5f);
    while ((tm + 1) * (tm + 2) / 2 <= t) tm++;
    while (tm * (tm + 1) / 2 > t) tm--;
    int tn = t - tm * (tm + 1) / 2;

    int n0 = tn * 128, m0 = tm * 128;
    const float* xb = x + (size_t)b * Cn * Nn;
    int tid = threadIdx.x, tx = tid & 15, ty = tid >> 4;

    float* As = sh;            // [32][128]
    float* Bs = sh + 32 * 128; // [32][128]

    float acc[8][8] = {};

    for (int kc = 0; kc < 64; kc += 32) {
        __syncthreads();
#pragma unroll
        for (int i = 0; i < 4; i++) {
            int f = tid + 256 * i;          // float4 index over 1024
            int c = f >> 5, c4 = (f & 31) * 4;
            *(float4*)&As[c * 128 + c4] = *(const float4*)&xb[(size_t)(kc + c) * Nn + n0 + c4];
            *(float4*)&Bs[c * 128 + c4] = *(const float4*)&xb[(size_t)(kc + c) * Nn + m0 + c4];
        }
        __syncthreads();
#pragma unroll 4
        for (int c = 0; c < 32; c++) {
            float4 a0 = *(float4*)&As[c * 128 + ty * 4];
            float4 a1 = *(float4*)&As[c * 128 + 64 + ty * 4];
            float4 b0 = *(float4*)&Bs[c * 128 + tx * 4];
            float4 b1 = *(float4*)&Bs[c * 128 + 64 + tx * 4];
            float av[8] = {a0.x, a0.y, a0.z, a0.w, a1.x, a1.y, a1.z, a1.w};
            float bv[8] = {b0.x, b0.y, b0.z, b0.w, b1.x, b1.y, b1.z, b1.w};
#pragma unroll
            for (int i = 0; i < 8; i++)
#pragma unroll
                for (int j = 0; j < 8; j++)
                    acc[i][j] = fmaf(av[i], bv[j], acc[i][j]);
        }
    }

    float xn[8], xm[8];
#pragma unroll
    for (int i = 0; i < 4; i++) {
        xn[i]     = g_xx[b * Nn + n0 + ty * 4 + i];
        xn[4 + i] = g_xx[b * Nn + n0 + 64 + ty * 4 + i];
        xm[i]     = g_xx[b * Nn + m0 + tx * 4 + i];
        xm[4 + i] = g_xx[b * Nn + m0 + 64 + tx * 4 + i];
    }

    float vv[8][8];
#pragma unroll
    for (int i = 0; i < 8; i++)
#pragma unroll
        for (int j = 0; j < 8; j++)
            vv[i][j] = 2.f * acc[i][j] - xn[i] - xm[j];

    float* Db = g_D + (size_t)b * Nn * Nn;

    // direct store: D[n][m]
#pragma unroll
    for (int i = 0; i < 8; i++) {
        int nl = (i < 4) ? (ty * 4 + i) : (64 + ty * 4 + i - 4);
        *(float4*)&Db[(size_t)(n0 + nl) * Nn + m0 + tx * 4] =
            make_float4(vv[i][0], vv[i][1], vv[i][2], vv[i][3]);
        *(float4*)&Db[(size_t)(n0 + nl) * Nn + m0 + 64 + tx * 4] =
            make_float4(vv[i][4], vv[i][5], vv[i][6], vv[i][7]);
    }

    // mirror store: D[m][n] via smem transpose (two 64-col halves)
    if (tm != tn) {
        float* Ts = sh;                       // [64][132]
#pragma unroll
        for (int h = 0; h < 2; h++) {
            __syncthreads();
#pragma unroll
            for (int i = 0; i < 8; i++) {
                int nl = (i < 4) ? (ty * 4 + i) : (64 + ty * 4 + i - 4);
#pragma unroll
                for (int j = 0; j < 4; j++)
                    Ts[(tx * 4 + j) * 132 + nl] = vv[i][h * 4 + j];
            }
            __syncthreads();
#pragma unroll
            for (int q = 0; q < 8; q++) {
                int f = tid + 256 * q;        // over 64*32 float4
                int mc = f >> 5, n4 = (f & 31) * 4;
                float4 w = *(float4*)&Ts[mc * 132 + n4];
                *(float4*)&Db[(size_t)(m0 + h * 64 + mc) * Nn + n0 + n4] = w;
            }
        }
    }
}

// ---------------- kernel 3: top-K=20 via 2-level radix (8-bit) + compaction ----------
// Only the SET of top-K indices matters downstream (sum/max over k). Ties at the
// exact threshold key resolved by smallest index -> identical set to stable top_k.
__global__ void __launch_bounds__(256) k_topk() {
    int row = blockIdx.x;                       // b*N + n
    const float4* d4 = (const float4*)(g_D + (size_t)row * Nn);
    int tid = threadIdx.x;                      // 256 threads, 8 elems each
    int lane = tid & 31, warp = tid >> 5;

    __shared__ int whist[8][256];               // per-warp pass-1 histograms
    __shared__ int hist[256];
    __shared__ int sgt[257];                    // suffix counts
    __shared__ int s_win, s_kp, s_cnt, s_cc1, s_cc2;
    __shared__ unsigned       ck[2048];         // pass-1 candidates: keys
    __shared__ unsigned short ci[2048];         //                    indices
    __shared__ unsigned       ck2[256];
    __shared__ unsigned short ci2[256];

    // load + convert to order-preserving uint keys (bigger key = bigger float)
    unsigned key[8];
    {
        float4 a = d4[tid * 2], b = d4[tid * 2 + 1];
        float f[8] = {a.x, a.y, a.z, a.w, b.x, b.y, b.z, b.w};
#pragma unroll
        for (int i = 0; i < 8; i++) {
            unsigned u = __float_as_uint(f[i]);
            key[i] = ((int)u < 0) ? ~u : (u | 0x80000000u);
        }
    }

#pragma unroll
    for (int w = 0; w < 8; w++) whist[w][tid] = 0;
    if (tid == 0) { s_cnt = 0; s_cc1 = 0; s_cc2 = 0; sgt[256] = 0; }
    __syncthreads();

    // ---- pass 1 histogram (top 8 bits), match-aggregated to kill conflicts ----
#pragma unroll
    for (int i = 0; i < 8; i++) {
        int b = key[i] >> 24;
        unsigned m = __match_any_sync(0xffffffffu, b);
        if (lane == (__ffs(m) - 1)) atomicAdd(&whist[warp][b], __popc(m));
    }
    __syncthreads();
    {
        int tot = 0;
#pragma unroll
        for (int w = 0; w < 8; w++) tot += whist[w][tid];
        hist[tid] = tot;
    }
    __syncthreads();
    if (tid < 32) {                              // suffix counts over 256 bins
        int base = tid * 8, l[8], run = 0;
#pragma unroll
        for (int j = 7; j >= 0; j--) { run += hist[base + j]; l[j] = run; }
        int tot = run, inc = tot;
#pragma unroll
        for (int off = 1; off < 32; off <<= 1) {
            int v = __shfl_down_sync(0xffffffffu, inc, off);
            if (tid + off < 32) inc += v;
        }
        int above = inc - tot;
#pragma unroll
        for (int j = 0; j < 8; j++) sgt[base + j] = l[j] + above;
    }
    __syncthreads();
    {
        int cg = sgt[tid], cgn = sgt[tid + 1];
        if (cg >= Kn && cgn < Kn) { s_win = tid; s_kp = Kn - cgn; }
    }
    __syncthreads();

    int win = s_win;
    int* op = g_idx + row * Kn;

    // ---- direct emit (> win) + ballot compaction (== win) ----
#pragma unroll
    for (int i = 0; i < 8; i++) {
        int b = key[i] >> 24;
        int e = tid * 8 + i;
        bool gt = b > win, eq = b == win;
        unsigned mgt = __ballot_sync(0xffffffffu, gt);
        unsigned meq = __ballot_sync(0xffffffffu, eq);
        int pg = 0, pe = 0;
        if (lane == 0) {
            if (mgt) pg = atomicAdd(&s_cnt, __popc(mgt));
            if (meq) pe = atomicAdd(&s_cc1, __popc(meq));
        }
        pg = __shfl_sync(0xffffffffu, pg, 0);
        pe = __shfl_sync(0xffffffffu, pe, 0);
        unsigned lml = (1u << lane) - 1u;
        if (gt) op[pg + __popc(mgt & lml)] = e;
        if (eq) {
            int p = pe + __popc(meq & lml);
            ck[p] = key[i]; ci[p] = (unsigned short)e;
        }
    }
    hist[tid] = 0;                               // prep pass-2 histogram
    __syncthreads();

    int cc1 = s_cc1, kp = s_kp;
    if (cc1 == kp) {                             // exact fit: all candidates in
        int base = Kn - kp;
        for (int i = tid; i < cc1; i += 256) op[base + i] = ci[i];
        return;
    }

    // ---- pass 2 histogram over candidates (bits 23:16, well-spread mantissa) ----
    for (int i = tid; i < cc1; i += 256) atomicAdd(&hist[(ck[i] >> 16) & 255], 1);
    __syncthreads();
    if (tid < 32) {
        int base = tid * 8, l[8], run = 0;
#pragma unroll
        for (int j = 7; j >= 0; j--) { run += hist[base + j]; l[j] = run; }
        int tot = run, inc = tot;
#pragma unroll
        for (int off = 1; off < 32; off <<= 1) {
            int v = __shfl_down_sync(0xffffffffu, inc, off);
            if (tid + off < 32) inc += v;
        }
        int above = inc - tot;
#pragma unroll
        for (int j = 0; j < 8; j++) sgt[base + j] = l[j] + above;
    }
    __syncthreads();
    {
        int cg = sgt[tid], cgn = sgt[tid + 1];
        if (cg >= kp && cgn < kp) { s_win = tid; s_kp = kp - cgn; }
    }
    __syncthreads();
    int win2 = s_win, kp2 = s_kp;

    for (int i = tid; i < cc1; i += 256) {
        int b = (ck[i] >> 16) & 255;
        if (b > win2) {
            op[atomicAdd(&s_cnt, 1)] = ci[i];    // definitely in (order arbitrary)
        } else if (b == win2) {
            int p = atomicAdd(&s_cc2, 1);
            if (p < 256) { ck2[p] = ck[i]; ci2[p] = ci[i]; }
        }
    }
    __syncthreads();

    int cc2 = s_cc2, base = s_cnt;               // base == Kn - kp2
    if (cc2 <= 256) {
        // exact rank among survivors by (key desc, idx asc)
        for (int i = tid; i < cc2; i += 256) {
            unsigned kk = ck2[i]; unsigned short xi = ci2[i];
            int r = 0;
            for (int j = 0; j < cc2; j++) {
                unsigned kj = ck2[j];
                r += (kj > kk) || (kj == kk && ci2[j] < xi);
            }
            if (r < kp2) op[base + r] = xi;
        }
    } else {
        // pathological overflow: exact rank over the full pass-1 candidate list
        for (int i = tid; i < cc1; i += 256) {
            if (((ck[i] >> 16) & 255) != win2) continue;
            unsigned kk = ck[i]; unsigned short xi = ci[i];
            int r = 0;
            for (int j = 0; j < cc1; j++) {
                if (((ck[j] >> 16) & 255) != win2) continue;
                unsigned kj = ck[j];
                r += (kj > kk) || (kj == kk && ci[j] < xi);
            }
            if (r < kp2) op[base + r] = xi;
        }
    }
}

// ---------------- kernel 4: U = Wd.x , Bse = (Wc-Wd).x  (o-contiguous layout) -----------
__global__ void k_uv(const float* __restrict__ x, const float* __restrict__ W) {
    int b = blockIdx.y;
    int m0 = blockIdx.x * 64;
    __shared__ float Wd[64 * 64];   // [c][o]
    __shared__ float Wf[64 * 64];   // [c][o]  (Wc - Wd)
    __shared__ float xs[64 * 64];   // [c][m]
    int tid = threadIdx.x;
#pragma unroll
    for (int i = 0; i < 16; i++) {
        int id = tid + 256 * i;
        int o = id >> 6, c = id & 63;
        float wd = W[o * 128 + c];
        float wc = W[o * 128 + 64 + c];
        Wd[c * 64 + o] = wd;
        Wf[c * 64 + o] = wc - wd;
        xs[id] = x[(size_t)b * Cn * Nn + (size_t)(id >> 6) * Nn + m0 + (id & 63)];
    }
    __syncthreads();

    int o = tid & 63, mq = tid >> 6;
    float aU[16], aD[16];
#pragma unroll
    for (int t = 0; t < 16; t++) { aU[t] = 0.f; aD[t] = 0.f; }

    for (int c = 0; c < 64; c++) {
        float wu = Wd[c * 64 + o];
        float wf = Wf[c * 64 + o];
#pragma unroll
        for (int t = 0; t < 16; t++) {
            float xv = xs[c * 64 + mq + t * 4];   // broadcast within warp
            aU[t] = fmaf(wu, xv, aU[t]);
            aD[t] = fmaf(wf, xv, aD[t]);
        }
    }
#pragma unroll
    for (int t = 0; t < 16; t++) {
        int m = m0 + mq + t * 4;
        g_U  [((size_t)b * Nn + m) * On + o] = aU[t];
        g_Bse[((size_t)b * Nn + m) * On + o] = aD[t];
    }
}

// ---------------- kernel 5: per-channel sum / sumsq of y over (b,n,k) ----------------
__global__ void k_stats() {
    int b = blockIdx.y;
    int n0 = blockIdx.x * 128;
    int tid = threadIdx.x;
    int o = tid & 63, g = tid >> 6;
    float s = 0.f, s2 = 0.f;
    for (int j = 0; j < 32; j++) {
        int n = n0 + g * 32 + j;
        float bse = g_Bse[((size_t)b * Nn + n) * On + o];
        const int* ip = g_idx + (b * Nn + n) * Kn;
#pragma unroll
        for (int k = 0; k < Kn; k++) {
            int m = ip[k];
            float y = g_U[((size_t)b * Nn + m) * On + o] + bse;
            s += y;
            s2 = fmaf(y, y, s2);
        }
    }
    __shared__ float ss[4][64], ss2[4][64];
    ss[g][o] = s; ss2[g][o] = s2;
    __syncthreads();
    if (g == 0) {
        double ts = (double)ss[0][o] + (double)ss[1][o] + (double)ss[2][o] + (double)ss[3][o];
        double t2 = (double)ss2[0][o] + (double)ss2[1][o] + (double)ss2[2][o] + (double)ss2[3][o];
        atomicAdd(&g_sum[o], ts);
        atomicAdd(&g_sumsq[o], t2);
    }
}

// ---------------- kernel 6: finalize BN affine ----------------
__global__ void k_fin(const float* __restrict__ gamma, const float* __restrict__ beta) {
    int o = threadIdx.x;
    double mean = g_sum[o] / (double)CNT_TOT;
    double var  = g_sumsq[o] / (double)CNT_TOT - mean * mean;
    float sc = gamma[o] * rsqrtf((float)var + 1e-5f);
    g_scale[o] = sc;
    g_shift[o] = beta[o] - (float)mean * sc;
}

// ---------------- kernel 7: normalize + leaky relu + max over k -> out[b][o][n] --------
__global__ void k_out(float* __restrict__ out) {
    int b = blockIdx.y;
    int n0 = blockIdx.x * 32;
    int tid = threadIdx.x;
    int o = tid & 63, nq = tid >> 6;
    __shared__ float sm[64 * 33];
    float sc = g_scale[o], sh = g_shift[o];
    for (int j = 0; j < 8; j++) {
        int nl = nq * 8 + j;
        int n = n0 + nl;
        float bse = g_Bse[((size_t)b * Nn + n) * On + o];
        const int* ip = g_idx + (b * Nn + n) * Kn;
        float mx = -FLT_MAX;
#pragma unroll
        for (int k = 0; k < Kn; k++) {
            int m = ip[k];
            float y  = g_U[((size_t)b * Nn + m) * On + o] + bse;
            float yn = fmaf(y, sc, sh);
            float a  = (yn >= 0.f) ? yn : 0.2f * yn;
            mx = fmaxf(mx, a);
        }
        sm[o * 33 + nl] = mx;
    }
    __syncthreads();
    int nl2 = tid & 31, og = tid >> 5;
#pragma unroll
    for (int j = 0; j < 8; j++) {
        int o2 = og * 8 + j;
        out[((size_t)b * On + o2) * Nn + n0 + nl2] = sm[o2 * 33 + nl2];
    }
}

// ---------------- launch ----------------
extern "C" void kernel_launch(void* const* d_in, const int* in_sizes, int n_in,
                              void* d_out, int out_size) {
    const float* x     = (const float*)d_in[0];
    const float* W     = (const float*)d_in[1];
    const float* gamma = (const float*)d_in[2];
    const float* beta  = (const float*)d_in[3];
    float* out = (float*)d_out;

    k_zero<<<1, 64>>>();
    k_xx<<<(Bn * Nn) / 256, 256>>>(x);

    dim3 gg(136, 16);                 // triangular tile set, 128x128 tiles
    k_gram<<<gg, 256>>>(x);

    k_topk<<<Bn * Nn, 256>>>();

    dim3 guv(Nn / 64, Bn);
    k_uv<<<guv, 256>>>(x, W);

    dim3 gst(16, Bn);
    k_stats<<<gst, 256>>>();

    k_fin<<<1, 64>>>(gamma, beta);

    dim3 go(Nn / 32, Bn);
    k_out<<<go, 256>>>(out);
}

// round 5
// speedup vs baseline: 1.4721x; 1.2488x over previous
#include <cuda_runtime.h>
#include <cfloat>

#define Bn 16
#define Cn 64
#define Nn 2048
#define On 64
#define Kn 20
#define CNT_TOT (16*2048*20)

// ---------------- scratch (static device globals; no runtime allocation) ----------------
__device__ float  g_D[(size_t)Bn*Nn*Nn];     // 256 MB neg_dist scratch
__device__ float  g_xx[Bn*Nn];               // squared norms
__device__ int    g_idx[Bn*Nn*Kn];           // top-K index sets (order arbitrary)
__device__ float  g_U[(size_t)Bn*Nn*On];     // U[b][m][o] = Wd . x  (o contiguous)
__device__ float  g_Bse[(size_t)Bn*Nn*On];   // (V-U)[b][n][o]
__device__ double g_sum[On], g_sumsq[On];
__device__ float  g_scale[On], g_shift[On];

// ---------------- kernel 0: zero the stats accumulators (graph replays!) ----------------
__global__ void k_zero() {
    int o = threadIdx.x;
    g_sum[o] = 0.0; g_sumsq[o] = 0.0;
}

// ---------------- kernel 1: xx[b,n] = sum_c x^2 ----------------
__global__ void k_xx(const float* __restrict__ x) {
    int id = blockIdx.x * blockDim.x + threadIdx.x;   // 0 .. B*N-1
    if (id >= Bn * Nn) return;
    int b = id / Nn, n = id % Nn;
    const float* xp = x + (size_t)b * Cn * Nn + n;
    float s = 0.f;
#pragma unroll
    for (int c = 0; c < Cn; c++) {
        float v = xp[(size_t)c * Nn];
        s = fmaf(v, v, s);
    }
    g_xx[id] = s;
}

// ---------------- kernel 2: neg_dist 128x128 tiles, 8x8 per thread ----------------
// Triangular grid (tm >= tn); mirror written via smem transpose.
__global__ void __launch_bounds__(256) k_gram(const float* __restrict__ x) {
    __shared__ __align__(16) float sh[64 * 132];   // As|Bs during compute, Ts after

    int t = blockIdx.x, b = blockIdx.y;
    int tm = (int)((sqrtf(8.f * t + 1.f) - 1.f) * 0.5f);
    while ((tm + 1) * (tm + 2) / 2 <= t) tm++;
    while (tm * (tm + 1) / 2 > t) tm--;
    int tn = t - tm * (tm + 1) / 2;

    int n0 = tn * 128, m0 = tm * 128;
    const float* xb = x + (size_t)b * Cn * Nn;
    int tid = threadIdx.x, tx = tid & 15, ty = tid >> 4;

    float* As = sh;            // [32][128]
    float* Bs = sh + 32 * 128; // [32][128]

    float acc[8][8] = {};

    for (int kc = 0; kc < 64; kc += 32) {
        __syncthreads();
#pragma unroll
        for (int i = 0; i < 4; i++) {
            int f = tid + 256 * i;          // float4 index over 1024
            int c = f >> 5, c4 = (f & 31) * 4;
            *(float4*)&As[c * 128 + c4] = *(const float4*)&xb[(size_t)(kc + c) * Nn + n0 + c4];
            *(float4*)&Bs[c * 128 + c4] = *(const float4*)&xb[(size_t)(kc + c) * Nn + m0 + c4];
        }
        __syncthreads();
#pragma unroll 4
        for (int c = 0; c < 32; c++) {
            float4 a0 = *(float4*)&As[c * 128 + ty * 4];
            float4 a1 = *(float4*)&As[c * 128 + 64 + ty * 4];
            float4 b0 = *(float4*)&Bs[c * 128 + tx * 4];
            float4 b1 = *(float4*)&Bs[c * 128 + 64 + tx * 4];
            float av[8] = {a0.x, a0.y, a0.z, a0.w, a1.x, a1.y, a1.z, a1.w};
            float bv[8] = {b0.x, b0.y, b0.z, b0.w, b1.x, b1.y, b1.z, b1.w};
#pragma unroll
            for (int i = 0; i < 8; i++)
#pragma unroll
                for (int j = 0; j < 8; j++)
                    acc[i][j] = fmaf(av[i], bv[j], acc[i][j]);
        }
    }

    float xn[8], xm[8];
#pragma unroll
    for (int i = 0; i < 4; i++) {
        xn[i]     = g_xx[b * Nn + n0 + ty * 4 + i];
        xn[4 + i] = g_xx[b * Nn + n0 + 64 + ty * 4 + i];
        xm[i]     = g_xx[b * Nn + m0 + tx * 4 + i];
        xm[4 + i] = g_xx[b * Nn + m0 + 64 + tx * 4 + i];
    }

    float vv[8][8];
#pragma unroll
    for (int i = 0; i < 8; i++)
#pragma unroll
        for (int j = 0; j < 8; j++)
            vv[i][j] = 2.f * acc[i][j] - xn[i] - xm[j];

    float* Db = g_D + (size_t)b * Nn * Nn;

    // direct store: D[n][m]
#pragma unroll
    for (int i = 0; i < 8; i++) {
        int nl = (i < 4) ? (ty * 4 + i) : (64 + ty * 4 + i - 4);
        *(float4*)&Db[(size_t)(n0 + nl) * Nn + m0 + tx * 4] =
            make_float4(vv[i][0], vv[i][1], vv[i][2], vv[i][3]);
        *(float4*)&Db[(size_t)(n0 + nl) * Nn + m0 + 64 + tx * 4] =
            make_float4(vv[i][4], vv[i][5], vv[i][6], vv[i][7]);
    }

    // mirror store: D[m][n] via smem transpose (two 64-col halves)
    if (tm != tn) {
        float* Ts = sh;                       // [64][132]
#pragma unroll
        for (int h = 0; h < 2; h++) {
            __syncthreads();
#pragma unroll
            for (int i = 0; i < 8; i++) {
                int nl = (i < 4) ? (ty * 4 + i) : (64 + ty * 4 + i - 4);
#pragma unroll
                for (int j = 0; j < 4; j++)
                    Ts[(tx * 4 + j) * 132 + nl] = vv[i][h * 4 + j];
            }
            __syncthreads();
#pragma unroll
            for (int q = 0; q < 8; q++) {
                int f = tid + 256 * q;        // over 64*32 float4
                int mc = f >> 5, n4 = (f & 31) * 4;
                float4 w = *(float4*)&Ts[mc * 132 + n4];
                *(float4*)&Db[(size_t)(m0 + h * 64 + mc) * Nn + n0 + n4] = w;
            }
        }
    }
}

// ---------------- kernel 3: top-K=20 via value-scaled 256-bin histogram select ----------
// Bin on (v - rowmin) * 255/(rowmax - rowmin): the bulk of the row lands mid-
// histogram, bins near the max are sparse. Only the SET of top-K indices matters
// downstream; threshold-bin ties resolved by exact (key desc, idx asc) rank ->
// identical set to stable top_k.
__global__ void __launch_bounds__(256) k_topk() {
    int row = blockIdx.x;                       // b*N + n
    const float4* d4 = (const float4*)(g_D + (size_t)row * Nn);
    int tid = threadIdx.x;                      // 256 threads, 8 elems each
    int lane = tid & 31, warp = tid >> 5;

    __shared__ float s_wmax[8], s_wmin[8];
    __shared__ float s_M, s_m;
    __shared__ int   hist[257];                 // suffix-scanned in place
    __shared__ int   s_win, s_kp, s_cnt, s_cc;
    __shared__ unsigned       ck[2048];         // threshold-bin candidates
    __shared__ unsigned short ci[2048];

    float4 a = d4[tid * 2], b4 = d4[tid * 2 + 1];
    float f[8] = {a.x, a.y, a.z, a.w, b4.x, b4.y, b4.z, b4.w};

    // row max / min (registers + shfl only)
    float mx = f[0], mn = f[0];
#pragma unroll
    for (int i = 1; i < 8; i++) { mx = fmaxf(mx, f[i]); mn = fminf(mn, f[i]); }
#pragma unroll
    for (int off = 16; off; off >>= 1) {
        mx = fmaxf(mx, __shfl_xor_sync(0xffffffffu, mx, off));
        mn = fminf(mn, __shfl_xor_sync(0xffffffffu, mn, off));
    }
    if (lane == 0) { s_wmax[warp] = mx; s_wmin[warp] = mn; }
    hist[tid] = 0;
    if (tid == 0) { hist[256] = 0; s_cnt = 0; s_cc = 0; }
    __syncthreads();
    if (tid == 0) {
        float M = s_wmax[0], m = s_wmin[0];
#pragma unroll
        for (int w = 1; w < 8; w++) { M = fmaxf(M, s_wmax[w]); m = fminf(m, s_wmin[w]); }
        s_M = M; s_m = m;
    }
    __syncthreads();

    float m = s_m, range = s_M - s_m;
    float sc = (range > 0.f) ? (255.f / range) : 0.f;

    int bin[8];
#pragma unroll
    for (int i = 0; i < 8; i++) {
        int bb = (int)((f[i] - m) * sc);
        bin[i] = bb > 255 ? 255 : bb;
        atomicAdd(&hist[bin[i]], 1);
    }
    __syncthreads();

    // suffix counts in place: hist[b] = #elems with bin >= b (warp 0 only)
    if (tid < 32) {
        int base = tid * 8, l[8], run = 0;
#pragma unroll
        for (int j = 7; j >= 0; j--) { run += hist[base + j]; l[j] = run; }
        int tot = run, inc = tot;
#pragma unroll
        for (int off = 1; off < 32; off <<= 1) {
            int v = __shfl_down_sync(0xffffffffu, inc, off);
            if (tid + off < 32) inc += v;
        }
        int above = inc - tot;
#pragma unroll
        for (int j = 0; j < 8; j++) hist[base + j] = l[j] + above;
    }
    __syncthreads();
    {
        int cg = hist[tid], cgn = hist[tid + 1];
        if (cg >= Kn && cgn < Kn) { s_win = tid; s_kp = Kn - cgn; }
    }
    __syncthreads();

    int win = s_win;
    int* op = g_idx + row * Kn;

    // direct emit (> win, order arbitrary) + ballot compaction (== win)
#pragma unroll
    for (int i = 0; i < 8; i++) {
        int e = tid * 8 + i;
        bool gt = bin[i] > win, eq = bin[i] == win;
        unsigned mgt = __ballot_sync(0xffffffffu, gt);
        unsigned meq = __ballot_sync(0xffffffffu, eq);
        int pg = 0, pe = 0;
        if (lane == 0) {
            if (mgt) pg = atomicAdd(&s_cnt, __popc(mgt));
            if (meq) pe = atomicAdd(&s_cc, __popc(meq));
        }
        pg = __shfl_sync(0xffffffffu, pg, 0);
        pe = __shfl_sync(0xffffffffu, pe, 0);
        unsigned lml = (1u << lane) - 1u;
        if (gt) op[pg + __popc(mgt & lml)] = e;
        if (eq) {
            unsigned u = __float_as_uint(f[i]);
            unsigned key = ((int)u < 0) ? ~u : (u | 0x80000000u);
            int p = pe + __popc(meq & lml);
            ck[p] = key; ci[p] = (unsigned short)e;
        }
    }
    __syncthreads();

    int cc = s_cc, kp = s_kp, base = s_cnt;      // base == Kn - kp
    // exact rank among threshold-bin candidates by (key desc, idx asc)
    for (int i = tid; i < cc; i += 256) {
        unsigned kk = ck[i]; unsigned short xi = ci[i];
        int r = 0;
        for (int j = 0; j < cc; j++) {
            unsigned kj = ck[j];
            r += (kj > kk) || (kj == kk && ci[j] < xi);
        }
        if (r < kp) op[base + r] = xi;
    }
}

// ---------------- kernel 4: U = Wd.x , Bse = (Wc-Wd).x  (o-contiguous layout) -----------
__global__ void k_uv(const float* __restrict__ x, const float* __restrict__ W) {
    int b = blockIdx.y;
    int m0 = blockIdx.x * 64;
    __shared__ float Wd[64 * 64];   // [c][o]
    __shared__ float Wf[64 * 64];   // [c][o]  (Wc - Wd)
    __shared__ float xs[64 * 64];   // [c][m]
    int tid = threadIdx.x;
#pragma unroll
    for (int i = 0; i < 16; i++) {
        int id = tid + 256 * i;
        int o = id >> 6, c = id & 63;
        float wd = W[o * 128 + c];
        float wc = W[o * 128 + 64 + c];
        Wd[c * 64 + o] = wd;
        Wf[c * 64 + o] = wc - wd;
        xs[id] = x[(size_t)b * Cn * Nn + (size_t)(id >> 6) * Nn + m0 + (id & 63)];
    }
    __syncthreads();

    int o = tid & 63, mq = tid >> 6;
    float aU[16], aD[16];
#pragma unroll
    for (int t = 0; t < 16; t++) { aU[t] = 0.f; aD[t] = 0.f; }

    for (int c = 0; c < 64; c++) {
        float wu = Wd[c * 64 + o];
        float wf = Wf[c * 64 + o];
#pragma unroll
        for (int t = 0; t < 16; t++) {
            float xv = xs[c * 64 + mq + t * 4];   // broadcast within warp
            aU[t] = fmaf(wu, xv, aU[t]);
            aD[t] = fmaf(wf, xv, aD[t]);
        }
    }
#pragma unroll
    for (int t = 0; t < 16; t++) {
        int m = m0 + mq + t * 4;
        g_U  [((size_t)b * Nn + m) * On + o] = aU[t];
        g_Bse[((size_t)b * Nn + m) * On + o] = aD[t];
    }
}

// ---------------- kernel 5: per-channel sum / sumsq of y over (b,n,k) ----------------
__global__ void k_stats() {
    int b = blockIdx.y;
    int n0 = blockIdx.x * 128;
    int tid = threadIdx.x;
    int o = tid & 63, g = tid >> 6;
    float s = 0.f, s2 = 0.f;
    for (int j = 0; j < 32; j++) {
        int n = n0 + g * 32 + j;
        float bse = g_Bse[((size_t)b * Nn + n) * On + o];
        const int* ip = g_idx + (b * Nn + n) * Kn;
#pragma unroll
        for (int k = 0; k < Kn; k++) {
            int m = ip[k];
            float y = g_U[((size_t)b * Nn + m) * On + o] + bse;
            s += y;
            s2 = fmaf(y, y, s2);
        }
    }
    __shared__ float ss[4][64], ss2[4][64];
    ss[g][o] = s; ss2[g][o] = s2;
    __syncthreads();
    if (g == 0) {
        double ts = (double)ss[0][o] + (double)ss[1][o] + (double)ss[2][o] + (double)ss[3][o];
        double t2 = (double)ss2[0][o] + (double)ss2[1][o] + (double)ss2[2][o] + (double)ss2[3][o];
        atomicAdd(&g_sum[o], ts);
        atomicAdd(&g_sumsq[o], t2);
    }
}

// ---------------- kernel 6: finalize BN affine ----------------
__global__ void k_fin(const float* __restrict__ gamma, const float* __restrict__ beta) {
    int o = threadIdx.x;
    double mean = g_sum[o] / (double)CNT_TOT;
    double var  = g_sumsq[o] / (double)CNT_TOT - mean * mean;
    float sc = gamma[o] * rsqrtf((float)var + 1e-5f);
    g_scale[o] = sc;
    g_shift[o] = beta[o] - (float)mean * sc;
}

// ---------------- kernel 7: normalize + leaky relu + max over k -> out[b][o][n] --------
__global__ void k_out(float* __restrict__ out) {
    int b = blockIdx.y;
    int n0 = blockIdx.x * 32;
    int tid = threadIdx.x;
    int o = tid & 63, nq = tid >> 6;
    __shared__ float sm[64 * 33];
    float sc = g_scale[o], sh = g_shift[o];
    for (int j = 0; j < 8; j++) {
        int nl = nq * 8 + j;
        int n = n0 + nl;
        float bse = g_Bse[((size_t)b * Nn + n) * On + o];
        const int* ip = g_idx + (b * Nn + n) * Kn;
        float mx = -FLT_MAX;
#pragma unroll
        for (int k = 0; k < Kn; k++) {
            int m = ip[k];
            float y  = g_U[((size_t)b * Nn + m) * On + o] + bse;
            float yn = fmaf(y, sc, sh);
            float a  = (yn >= 0.f) ? yn : 0.2f * yn;
            mx = fmaxf(mx, a);
        }
        sm[o * 33 + nl] = mx;
    }
    __syncthreads();
    int nl2 = tid & 31, og = tid >> 5;
#pragma unroll
    for (int j = 0; j < 8; j++) {
        int o2 = og * 8 + j;
        out[((size_t)b * On + o2) * Nn + n0 + nl2] = sm[o2 * 33 + nl2];
    }
}

// ---------------- launch ----------------
extern "C" void kernel_launch(void* const* d_in, const int* in_sizes, int n_in,
                              void* d_out, int out_size) {
    const float* x     = (const float*)d_in[0];
    const float* W     = (const float*)d_in[1];
    const float* gamma = (const float*)d_in[2];
    const float* beta  = (const float*)d_in[3];
    float* out = (float*)d_out;

    k_zero<<<1, 64>>>();
    k_xx<<<(Bn * Nn) / 256, 256>>>(x);

    dim3 gg(136, 16);                 // triangular tile set, 128x128 tiles
    k_gram<<<gg, 256>>>(x);

    k_topk<<<Bn * Nn, 256>>>();

    dim3 guv(Nn / 64, Bn);
    k_uv<<<guv, 256>>>(x, W);

    dim3 gst(16, Bn);
    k_stats<<<gst, 256>>>();

    k_fin<<<1, 64>>>(gamma, beta);

    dim3 go(Nn / 32, Bn);
    k_out<<<go, 256>>>(out);
}